// round 14
// baseline (speedup 1.0000x reference)
#include <cuda_runtime.h>
#include <cuda_fp16.h>
#include <math.h>
#include <stdint.h>

typedef unsigned long long ull;

// ---------------- constants ----------------
#define BS_     2048
#define A_      32
#define ROWS    (BS_ * A_)     // 65536
#define MT_     (ROWS / 128)   // 512 row-blocks
#define IN_DIM  256
#define HID     256
#define NH      4
#define HD      16
#define CV      16
#define TOPK    8
#define NACT    20
#define QKVG_N  196
#define NEGV    (-1e10f)

#define M_NONE    0
#define M_RELU    1
#define M_QKVG    2
#define M_RELU_AF 3

// ---------------- scratch (device globals; no allocation) ----------------
__device__ float g_gi  [ROWS * 3 * HID];
__device__ float g_gh  [ROWS * 3 * HID];
__device__ float g_qkvg[ROWS * QKVG_N];
__device__ float g_p1  [ROWS * HID];
__device__ float g_wq  [QKVG_N * HID];
__device__ float g_bq  [QKVG_N];
// fragment-tiled fp16 hi/lo (uint32 words; block = 2048 words: [hi 1024][lo 1024])
__device__ uint32_t g_in_h2 [MT_ * 16 * 2048];
__device__ uint32_t g_hid_h2[MT_ * 16 * 2048];
__device__ uint32_t g_x_h2  [MT_ * 16 * 2048];
__device__ uint32_t g_h_h2  [MT_ * 16 * 2048];
__device__ uint32_t g_msg_h2[MT_ * 4 * 2048];
__device__ uint32_t g_wfc1_h2[2 * 16 * 2048];
__device__ uint32_t g_wih_h2 [6 * 16 * 2048];
__device__ uint32_t g_whh_h2 [6 * 16 * 2048];
__device__ uint32_t g_wq_h2  [2 * 16 * 2048];
__device__ uint32_t g_wp1_h2 [2 * 20 * 2048];

// ---------------- helpers ----------------
__device__ __forceinline__ float sigmoidf_(float x) { return 1.0f / (1.0f + expf(-x)); }

__device__ __forceinline__ void h2pair(float x, float y, uint32_t& hi, uint32_t& lo) {
    __half hx = __float2half_rn(x), hy = __float2half_rn(y);
    float rx = x - __half2float(hx), ry = y - __half2float(hy);
    __half2 H = __halves2half2(hx, hy);
    __half2 L = __halves2half2(__float2half_rn(rx), __float2half_rn(ry));
    hi = *reinterpret_cast<uint32_t*>(&H);
    lo = *reinterpret_cast<uint32_t*>(&L);
}

__device__ __forceinline__ void mma_f16(float* c, const uint32_t* a, const uint32_t* b) {
    asm volatile(
        "mma.sync.aligned.m16n8k16.row.col.f32.f16.f16.f32 "
        "{%0,%1,%2,%3}, {%4,%5,%6,%7}, {%8,%9}, {%0,%1,%2,%3};"
        : "+f"(c[0]), "+f"(c[1]), "+f"(c[2]), "+f"(c[3])
        : "r"(a[0]), "r"(a[1]), "r"(a[2]), "r"(a[3]), "r"(b[0]), "r"(b[1]));
}

// ---------------- split kernels: fp32 -> fragment-tiled fp16 hi/lo ----------------
// AF (A operand): block (mt,kt) = 256 threads: word idx = mf*128 + lane*4 + reg,
//   reg = khalf*2 + rhi; value pair = (A[row][k], A[row][k+1]),
//   row = mt*128 + mf*16 + rhi*8 + gid, k = kt*16 + khalf*8 + tg*2; lane = gid*4+tg.
__global__ void split_a(const float* __restrict__ src, uint32_t* __restrict__ dst,
                        int K, int total)
{
    int t = blockIdx.x * blockDim.x + threadIdx.x;
    if (t >= total) return;
    int KT = K / 16;
    int li = t & 255, blkid = t >> 8;          // 256 threads per block (mf 0..7)
    int kt = blkid % KT, mt = blkid / KT;
    int mf = li >> 5, lane = li & 31, gid = lane >> 2, tg = lane & 3;
    int row0 = mt * 128 + mf * 16 + gid;
    int k0 = kt * 16 + tg * 2;
    const float* p = src + (size_t)row0 * K + k0;
    float2 a00 = *(const float2*)(p);            // khalf0 rhi0
    float2 a01 = *(const float2*)(p + 8 * K);    // khalf0 rhi1
    float2 a10 = *(const float2*)(p + 8);        // khalf1 rhi0
    float2 a11 = *(const float2*)(p + 8 * K + 8);
    uint32_t h0,l0,h1,l1,h2_,l2,h3,l3;
    h2pair(a00.x, a00.y, h0, l0); h2pair(a01.x, a01.y, h1, l1);
    h2pair(a10.x, a10.y, h2_, l2); h2pair(a11.x, a11.y, h3, l3);
    size_t blk = (size_t)blkid * 2048;
    int idx = mf * 128 + lane * 4;
    *(uint4*)(dst + blk + idx)        = make_uint4(h0, h1, h2_, h3);
    *(uint4*)(dst + blk + 1024 + idx) = make_uint4(l0, l1, l2, l3);
}

// BF (B operand): block (nt,kt) = 512 threads: word idx = nf*64 + lane*2 + khalf,
//   value pair = (B[n][k], B[n][k+1]), n = nt*128 + nf*8 + gid, k = kt*16 + khalf*8 + tg*2.
__global__ void split_w(const float* __restrict__ src, uint32_t* __restrict__ dst,
                        int N, int K, int total)
{
    int t = blockIdx.x * blockDim.x + threadIdx.x;
    if (t >= total) return;
    int KT = K / 16;
    int li = t & 511, blkid = t >> 9;
    int kt = blkid % KT, nt = blkid / KT;
    int nf = li >> 5, lane = li & 31, gid = lane >> 2, tg = lane & 3;
    int n = nt * 128 + nf * 8 + gid;
    int k0 = kt * 16 + tg * 2;
    float2 b0 = make_float2(0.f, 0.f), b1 = b0;
    if (n < N) {
        b0 = *(const float2*)(src + (size_t)n * K + k0);
        b1 = *(const float2*)(src + (size_t)n * K + k0 + 8);
    }
    uint32_t h0,l0,h1,l1;
    h2pair(b0.x, b0.y, h0, l0);
    h2pair(b1.x, b1.y, h1, l1);
    size_t blk = (size_t)blkid * 2048;
    int idx = nf * 64 + lane * 2;
    *(uint2*)(dst + blk + idx)        = make_uint2(h0, h1);
    *(uint2*)(dst + blk + 1024 + idx) = make_uint2(l0, l1);
}

// ---------------- 2xFP16 (3-term) GEMM on pre-split fragment-tiled operands ----------
#define TG_SMEM 32768

__global__ __launch_bounds__(256, 2) void tgemm_h2(
    const uint32_t* __restrict__ afA1, const uint32_t* __restrict__ afA2, int KT1, int KT2,
    const uint32_t* __restrict__ bfB, const float* __restrict__ bias,
    float* __restrict__ C, uint32_t* __restrict__ Caf, int ktc,
    int ldc, int N, int mode)
{
    extern __shared__ uint32_t smw[];

    const int tid = threadIdx.x;
    const int lane = tid & 31;
    const int wid = tid >> 5;
    const int wm = wid & 1;
    const int wn = wid >> 1;
    const int mt = blockIdx.y;
    const int nt = blockIdx.x;
    const int KT = KT1 + KT2;

    const uint32_t* baseA1 = afA1 + (size_t)mt * KT1 * 2048;
    const uint32_t* baseA2 = afA2 + (size_t)mt * KT2 * 2048;
    const uint32_t* baseB  = bfB  + (size_t)nt * KT * 2048;

    float acc[4][4][4];
#pragma unroll
    for (int i = 0; i < 4; i++)
#pragma unroll
        for (int j = 0; j < 4; j++)
#pragma unroll
            for (int r = 0; r < 4; r++) acc[i][j][r] = 0.f;

    uint4 f0, f1, f2, f3;
    auto ldg = [&](int c) {
        const uint32_t* sA = (c < KT1) ? baseA1 + c * 2048 : baseA2 + (c - KT1) * 2048;
        const uint32_t* sB = baseB + c * 2048;
        f0 = *(const uint4*)(sA + tid * 4);
        f1 = *(const uint4*)(sA + 1024 + tid * 4);
        f2 = *(const uint4*)(sB + tid * 4);
        f3 = *(const uint4*)(sB + 1024 + tid * 4);
    };
    auto sts = [&](int buf) {
        uint32_t* s = smw + buf * 4096 + tid * 4;
        *(uint4*)(s)        = f0;
        *(uint4*)(s + 1024) = f1;
        *(uint4*)(s + 2048) = f2;
        *(uint4*)(s + 3072) = f3;
    };

    ldg(0); sts(0);
    __syncthreads();

    for (int c = 0; c < KT; c++) {
        if (c + 1 < KT) ldg(c + 1);

        const uint32_t* sw = smw + (c & 1) * 4096;
        uint32_t bh[4][2], bl[4][2];
#pragma unroll
        for (int j = 0; j < 4; j++) {
            const int nf = wn * 4 + j;
            uint2 vh = *(const uint2*)(sw + 2048 + nf * 64 + lane * 2);
            uint2 vl = *(const uint2*)(sw + 3072 + nf * 64 + lane * 2);
            bh[j][0] = vh.x; bh[j][1] = vh.y;
            bl[j][0] = vl.x; bl[j][1] = vl.y;
        }
#pragma unroll
        for (int i = 0; i < 4; i++) {
            const int mf = wm * 4 + i;
            uint4 vh = *(const uint4*)(sw + mf * 128 + lane * 4);
            uint4 vl = *(const uint4*)(sw + 1024 + mf * 128 + lane * 4);
            uint32_t ah[4] = {vh.x, vh.y, vh.z, vh.w};
            uint32_t al[4] = {vl.x, vl.y, vl.z, vl.w};
#pragma unroll
            for (int j = 0; j < 4; j++) {
                mma_f16(acc[i][j], al, bh[j]);
                mma_f16(acc[i][j], ah, bl[j]);
                mma_f16(acc[i][j], ah, bh[j]);
            }
        }

        if (c + 1 < KT) sts((c + 1) & 1);
        __syncthreads();
    }

    // ---- epilogue ----
    const int gid = lane >> 2;
    const int tig = lane & 3;
#pragma unroll
    for (int i = 0; i < 4; i++) {
        const int rowl = wm * 64 + i * 16 + gid;       // local row (rhi=0), +8 for rhi=1
#pragma unroll
        for (int j = 0; j < 4; j++) {
            const int col = nt * 128 + wn * 32 + j * 8 + tig * 2;
            if (mode == M_RELU_AF) {
                float b0 = bias[col], b1 = bias[col + 1];
                float v0 = fmaxf(acc[i][j][0] + b0, 0.f);
                float v1 = fmaxf(acc[i][j][1] + b1, 0.f);
                float v2 = fmaxf(acc[i][j][2] + b0, 0.f);
                float v3 = fmaxf(acc[i][j][3] + b1, 0.f);
                int kt = col >> 4, kin = col & 15;
                int khalf = kin >> 3, tigk = (kin >> 1) & 3;
                int mf = rowl >> 4;
                int idx = mf * 128 + (gid * 4 + tigk) * 4 + khalf * 2;
                size_t blk = ((size_t)mt * ktc + kt) * 2048;
                uint32_t h, l;
                h2pair(v0, v1, h, l);
                Caf[blk + idx] = h;        Caf[blk + 1024 + idx] = l;
                h2pair(v2, v3, h, l);
                Caf[blk + idx + 1] = h;    Caf[blk + 1024 + idx + 1] = l;
            } else if (col < N) {
                const int row0 = mt * 128 + rowl;
                float b0 = bias[col], b1 = bias[col + 1];
                float v0 = acc[i][j][0] + b0, v1 = acc[i][j][1] + b1;
                float v2 = acc[i][j][2] + b0, v3 = acc[i][j][3] + b1;
                if (mode == M_RELU) {
                    v0 = fmaxf(v0, 0.f); v1 = fmaxf(v1, 0.f);
                    v2 = fmaxf(v2, 0.f); v3 = fmaxf(v3, 0.f);
                } else if (mode == M_QKVG && col >= 192) {
                    v0 = sigmoidf_(v0); v1 = sigmoidf_(v1);
                    v2 = sigmoidf_(v2); v3 = sigmoidf_(v3);
                }
                *(float2*)(C + (size_t)row0 * ldc + col)       = make_float2(v0, v1);
                *(float2*)(C + (size_t)(row0 + 8) * ldc + col) = make_float2(v2, v3);
            }
        }
    }
}

// ---------------- SIMT f32x2 GEMM (p2, N=20) ----------------
__device__ __forceinline__ ull pk2(float x) {
    ull r; asm("mov.b64 %0, {%1, %1};" : "=l"(r) : "f"(x)); return r;
}
__device__ __forceinline__ ull pk(float x, float y) {
    ull r; asm("mov.b64 %0, {%1, %2};" : "=l"(r) : "f"(x), "f"(y)); return r;
}
__device__ __forceinline__ void fma2(ull& d, ull a, ull b) {
    asm("fma.rn.f32x2 %0, %1, %2, %0;" : "+l"(d) : "l"(a), "l"(b));
}
__device__ __forceinline__ void unpk(ull v, float& x, float& y) {
    asm("mov.b64 {%0, %1}, %2;" : "=f"(x), "=f"(y) : "l"(v));
}

#define BM 128
#define BK 16
template<int BN>
__global__ __launch_bounds__(256, 2) void gemm8x8(
    const float* __restrict__ A1, const float* __restrict__ B, const float* __restrict__ bias,
    float* __restrict__ C, int ldc, int N, int K, int lda)
{
    constexpr int TN  = BN / 16;
    constexpr int PAD = 4;
    __shared__ __align__(16) float As[BK][BM + PAD];
    __shared__ __align__(16) float Bs[BK][BN + PAD];

    const int tid = threadIdx.x;
    const int m0 = blockIdx.y * BM;
    const int n0 = blockIdx.x * BN;
    const int tx = tid & 15;
    const int ty = tid >> 4;

    ull acc[8][TN / 2];
#pragma unroll
    for (int i = 0; i < 8; i++)
#pragma unroll
        for (int p = 0; p < TN / 2; p++) acc[i][p] = 0ull;

    for (int k0 = 0; k0 < K; k0 += BK) {
#pragma unroll
        for (int r = 0; r < 2; r++) {
            int e = tid + r * 256;
            int row = e >> 2;
            int kq = (e & 3) * 4;
            float4 v = *(const float4*)(A1 + (size_t)(m0 + row) * lda + k0 + kq);
            As[kq + 0][row] = v.x; As[kq + 1][row] = v.y;
            As[kq + 2][row] = v.z; As[kq + 3][row] = v.w;
        }
#pragma unroll
        for (int r = 0; r < BN / 64; r++) {
            int e = tid + r * 256;
            int col = e >> 2;
            int kq = (e & 3) * 4;
            float4 v = make_float4(0.f, 0.f, 0.f, 0.f);
            if (n0 + col < N) v = *(const float4*)(B + (size_t)(n0 + col) * K + k0 + kq);
            Bs[kq + 0][col] = v.x; Bs[kq + 1][col] = v.y;
            Bs[kq + 2][col] = v.z; Bs[kq + 3][col] = v.w;
        }
        __syncthreads();

#pragma unroll
        for (int kk = 0; kk < BK; kk++) {
            float4 a0 = *(const float4*)&As[kk][ty * 8];
            float4 a1 = *(const float4*)&As[kk][ty * 8 + 4];
            float am[8] = {a0.x, a0.y, a0.z, a0.w, a1.x, a1.y, a1.z, a1.w};
            float bn_[TN];
#pragma unroll
            for (int q = 0; q < TN / 4; q++) {
                float4 b = *(const float4*)&Bs[kk][tx * TN + q * 4];
                bn_[q * 4 + 0] = b.x; bn_[q * 4 + 1] = b.y;
                bn_[q * 4 + 2] = b.z; bn_[q * 4 + 3] = b.w;
            }
            ull bp[TN / 2];
#pragma unroll
            for (int p = 0; p < TN / 2; p++) bp[p] = pk(bn_[2 * p], bn_[2 * p + 1]);
#pragma unroll
            for (int i = 0; i < 8; i++) {
                ull aa = pk2(am[i]);
#pragma unroll
                for (int p = 0; p < TN / 2; p++) fma2(acc[i][p], aa, bp[p]);
            }
        }
        __syncthreads();
    }

#pragma unroll
    for (int i = 0; i < 8; i++) {
        int row = m0 + ty * 8 + i;
        float vals[TN];
#pragma unroll
        for (int p = 0; p < TN / 2; p++) unpk(acc[i][p], vals[2 * p], vals[2 * p + 1]);
#pragma unroll
        for (int j = 0; j < TN; j++) {
            int col = n0 + tx * TN + j;
            if (col < N) C[(size_t)row * ldc + col] = vals[j] + bias[col];
        }
    }
}

// ---------------- pack q/k/v/g (fp32, feeds split_w) ----------------
__global__ void pack_qkvg(const float* __restrict__ qw, const float* __restrict__ qb,
                          const float* __restrict__ kw, const float* __restrict__ kb,
                          const float* __restrict__ vw, const float* __restrict__ vb,
                          const float* __restrict__ gw, const float* __restrict__ gb)
{
    int i = blockIdx.x * blockDim.x + threadIdx.x;
    const int total = QKVG_N * HID;
    if (i < total) {
        int row = i / HID, c = i - row * HID;
        float v;
        if      (row < 64)  v = qw[row * HID + c];
        else if (row < 128) v = kw[(row - 64) * HID + c];
        else if (row < 192) v = vw[(row - 128) * HID + c];
        else                v = gw[(row - 192) * HID + c];
        g_wq[i] = v;
    }
    if (i < QKVG_N) {
        float b;
        if      (i < 64)  b = qb[i];
        else if (i < 128) b = kb[i - 64];
        else if (i < 192) b = vb[i - 128];
        else              b = gb[i - 192];
        g_bq[i] = b;
    }
}

// ---------------- GRU gate fusion (writes h fp32 + h_h2 AF) ----------------
__global__ void gru_gates(const float* __restrict__ gi, const float* __restrict__ gh,
                          const float* __restrict__ hin, float* __restrict__ hout,
                          uint32_t* __restrict__ haf)
{
    int i4 = blockIdx.x * blockDim.x + threadIdx.x;
    if (i4 >= ROWS * (HID / 4)) return;
    int row = i4 >> 6;
    int c   = (i4 & 63) << 2;
    const float* gib = gi + (size_t)row * 768 + c;
    const float* ghb = gh + (size_t)row * 768 + c;
    float4 gir = *(const float4*)(gib);
    float4 giz = *(const float4*)(gib + 256);
    float4 gin = *(const float4*)(gib + 512);
    float4 ghr = *(const float4*)(ghb);
    float4 ghz = *(const float4*)(ghb + 256);
    float4 ghn = *(const float4*)(ghb + 512);
    float4 h0  = *(const float4*)(hin + (size_t)row * HID + c);
    float4 o;
    {
        float r = sigmoidf_(gir.x + ghr.x);
        float z = sigmoidf_(giz.x + ghz.x);
        float n = tanhf(gin.x + r * ghn.x);
        o.x = (1.f - z) * n + z * h0.x;
    }
    {
        float r = sigmoidf_(gir.y + ghr.y);
        float z = sigmoidf_(giz.y + ghz.y);
        float n = tanhf(gin.y + r * ghn.y);
        o.y = (1.f - z) * n + z * h0.y;
    }
    {
        float r = sigmoidf_(gir.z + ghr.z);
        float z = sigmoidf_(giz.z + ghz.z);
        float n = tanhf(gin.z + r * ghn.z);
        o.z = (1.f - z) * n + z * h0.z;
    }
    {
        float r = sigmoidf_(gir.w + ghr.w);
        float z = sigmoidf_(giz.w + ghz.w);
        float n = tanhf(gin.w + r * ghn.w);
        o.w = (1.f - z) * n + z * h0.w;
    }
    *(float4*)(hout + (size_t)row * HID + c) = o;

    // AF write (KT=16)
    int mt = row >> 7, rl = row & 127, mf = rl >> 4, rr = rl & 15;
    int gid8 = rr & 7, rhi = rr >> 3;
    int kt = c >> 4, kin = c & 15, khalf = kin >> 3, tg = (kin >> 1) & 3;
    size_t blk = ((size_t)mt * 16 + kt) * 2048;
    int idx = mf * 128 + (gid8 * 4 + tg) * 4 + khalf * 2 + rhi;
    uint32_t h, l;
    h2pair(o.x, o.y, h, l);
    haf[blk + idx] = h;       haf[blk + 1024 + idx] = l;
    h2pair(o.z, o.w, h, l);
    haf[blk + idx + 4] = h;   haf[blk + 1024 + idx + 4] = l;
}

// ---------------- per-batch sparse attention (writes msg_h2 AF, KT=4) ------------
__global__ __launch_bounds__(128) void attention_kernel(const float* __restrict__ qkvg,
                                                        uint32_t* __restrict__ msgaf)
{
    __shared__ float q_s[A_][64];
    __shared__ float k_s[A_][64];
    __shared__ float v_s[A_][64];
    __shared__ float g_s[A_][NH];

    const int b = blockIdx.x;
    const int tid = threadIdx.x;
    const float* base = qkvg + (size_t)b * A_ * QKVG_N;

    for (int idx = tid; idx < A_ * QKVG_N; idx += 128) {
        int r = idx / QKVG_N, c = idx - r * QKVG_N;
        float v = base[(size_t)r * QKVG_N + c];
        if      (c < 64)  q_s[r][c] = v;
        else if (c < 128) k_s[r][c - 64] = v;
        else if (c < 192) v_s[r][c - 128] = v;
        else              g_s[r][c - 192] = v;
    }
    __syncthreads();

    const int qa = tid >> 2;
    const int hh = tid & 3;
    const int hb = hh * HD;

    float qv[HD];
#pragma unroll
    for (int d = 0; d < HD; d++) qv[d] = q_s[qa][hb + d];

    float sc[A_];
#pragma unroll
    for (int ka = 0; ka < A_; ka++) {
        float s = 0.f;
#pragma unroll
        for (int d = 0; d < HD; d++) s += qv[d] * k_s[ka][hb + d];
        sc[ka] = (ka == qa) ? NEGV : s * 0.25f;
    }

    unsigned sel = 0;
    float maxv = NEGV;
    for (int it = 0; it < TOPK; it++) {
        float best = -INFINITY; int bi = 0;
#pragma unroll
        for (int ka = 0; ka < A_; ka++) {
            bool free_ = !((sel >> ka) & 1u);
            if (free_ && sc[ka] > best) { best = sc[ka]; bi = ka; }
        }
        sel |= (1u << bi);
        if (it == 0) maxv = best;
    }

    float sum = 0.f;
#pragma unroll
    for (int ka = 0; ka < A_; ka++) {
        float e = ((sel >> ka) & 1u) ? expf(sc[ka] - maxv) : 0.f;
        sc[ka] = e;
        sum += e;
    }
    float inv = 1.f / sum;

    float m[CV];
#pragma unroll
    for (int d = 0; d < CV; d++) m[d] = 0.f;
#pragma unroll
    for (int ka = 0; ka < A_; ka++) {
        float w = sc[ka];
#pragma unroll
        for (int d = 0; d < CV; d++) m[d] += w * v_s[ka][hb + d];
    }

    float gate = g_s[qa][hh];
    float scale = inv * gate;

    const int row = b * A_ + qa;
    int mt = row >> 7, rl = row & 127, mf = rl >> 4, rr = rl & 15;
    int gid8 = rr & 7, rhi = rr >> 3;
    size_t blk = ((size_t)mt * 4 + hh) * 2048;
#pragma unroll
    for (int p = 0; p < 8; p++) {
        int khalf = p >> 2, tg = p & 3;
        int idx = mf * 128 + (gid8 * 4 + tg) * 4 + khalf * 2 + rhi;
        uint32_t h, l;
        h2pair(m[2 * p] * scale, m[2 * p + 1] * scale, h, l);
        msgaf[blk + idx] = h;
        msgaf[blk + 1024 + idx] = l;
    }
}

// ---------------- launch ----------------
extern "C" void kernel_launch(void* const* d_in, const int* in_sizes, int n_in,
                              void* d_out, int out_size)
{
    const float* inputs = (const float*)d_in[0];
    const float* hidden = (const float*)d_in[1];
    const float* fc1_w  = (const float*)d_in[2];
    const float* fc1_b  = (const float*)d_in[3];
    const float* w_ih   = (const float*)d_in[4];
    const float* w_hh   = (const float*)d_in[5];
    const float* b_ih   = (const float*)d_in[6];
    const float* b_hh   = (const float*)d_in[7];
    const float* q_w    = (const float*)d_in[8];
    const float* q_b    = (const float*)d_in[9];
    const float* k_w    = (const float*)d_in[10];
    const float* k_b    = (const float*)d_in[11];
    const float* v_w    = (const float*)d_in[12];
    const float* v_b    = (const float*)d_in[13];
    const float* g_w    = (const float*)d_in[14];
    const float* g_b    = (const float*)d_in[15];
    const float* p1_w   = (const float*)d_in[16];
    const float* p1_b   = (const float*)d_in[17];
    const float* p2_w   = (const float*)d_in[18];
    const float* p2_b   = (const float*)d_in[19];

    float* out    = (float*)d_out;
    float* logits = out;                       // [65536, 20]
    float* hout   = out + (size_t)ROWS * NACT; // [65536, 256]

    float *gi, *gh, *qkvg, *p1, *wq, *bq;
    uint32_t *inh2, *hidh2, *xh2, *hh2, *msgh2, *wfc1, *wih, *whh, *wq2, *wp1;
    cudaGetSymbolAddress((void**)&gi,    g_gi);
    cudaGetSymbolAddress((void**)&gh,    g_gh);
    cudaGetSymbolAddress((void**)&qkvg,  g_qkvg);
    cudaGetSymbolAddress((void**)&p1,    g_p1);
    cudaGetSymbolAddress((void**)&wq,    g_wq);
    cudaGetSymbolAddress((void**)&bq,    g_bq);
    cudaGetSymbolAddress((void**)&inh2,  g_in_h2);
    cudaGetSymbolAddress((void**)&hidh2, g_hid_h2);
    cudaGetSymbolAddress((void**)&xh2,   g_x_h2);
    cudaGetSymbolAddress((void**)&hh2,   g_h_h2);
    cudaGetSymbolAddress((void**)&msgh2, g_msg_h2);
    cudaGetSymbolAddress((void**)&wfc1,  g_wfc1_h2);
    cudaGetSymbolAddress((void**)&wih,   g_wih_h2);
    cudaGetSymbolAddress((void**)&whh,   g_whh_h2);
    cudaGetSymbolAddress((void**)&wq2,   g_wq_h2);
    cudaGetSymbolAddress((void**)&wp1,   g_wp1_h2);

    const int MYT = MT_;   // 512

    // weight packs/splits (tiny)
    pack_qkvg<<<(QKVG_N * HID + 255) / 256, 256>>>(q_w, q_b, k_w, k_b, v_w, v_b, g_w, g_b);
    {
        int t1 = 2 * 16 * 512;
        int t2 = 6 * 16 * 512;
        int t3 = 2 * 20 * 512;
        split_w<<<(t1 + 255) / 256, 256>>>(fc1_w, wfc1, HID, IN_DIM, t1);
        split_w<<<(t2 + 255) / 256, 256>>>(w_ih, wih, 3 * HID, HID, t2);
        split_w<<<(t2 + 255) / 256, 256>>>(w_hh, whh, 3 * HID, HID, t2);
        split_w<<<(t1 + 255) / 256, 256>>>(wq, wq2, QKVG_N, HID, t1);
        split_w<<<(t3 + 255) / 256, 256>>>(p1_w, wp1, HID, HID + NH * CV, t3);
    }
    // input splits (256 threads per AF block)
    {
        int ta = MT_ * 16 * 256;
        split_a<<<(ta + 255) / 256, 256>>>(inputs, inh2, IN_DIM, ta);
        split_a<<<(ta + 255) / 256, 256>>>(hidden, hidh2, HID, ta);
    }

    // x = relu(fc1) -> x_h2 (AF, KT=16)
    tgemm_h2<<<dim3(2, MYT), 256, TG_SMEM>>>(
        inh2, inh2, 16, 0, wfc1, fc1_b, nullptr, xh2, 16, 0, HID, M_RELU_AF);
    // gi / gh (fp32)
    tgemm_h2<<<dim3(6, MYT), 256, TG_SMEM>>>(
        xh2, xh2, 16, 0, wih, b_ih, gi, nullptr, 0, 3 * HID, 3 * HID, M_NONE);
    tgemm_h2<<<dim3(6, MYT), 256, TG_SMEM>>>(
        hidh2, hidh2, 16, 0, whh, b_hh, gh, nullptr, 0, 3 * HID, 3 * HID, M_NONE);
    // h (fp32 out + AF)
    gru_gates<<<(ROWS * (HID / 4) + 255) / 256, 256>>>(gi, gh, hidden, hout, hh2);
    // qkvg (fp32, sigmoid on gate cols)
    tgemm_h2<<<dim3(2, MYT), 256, TG_SMEM>>>(
        hh2, hh2, 16, 0, wq2, bq, qkvg, nullptr, 0, QKVG_N, QKVG_N, M_QKVG);
    // attention -> msg_h2 (AF, KT=4)
    attention_kernel<<<BS_, 128>>>(qkvg, msgh2);
    // p1 = relu([h | msg] @ p1_w^T + b)  (split-A: 16 + 4 chunks)
    tgemm_h2<<<dim3(2, MYT), 256, TG_SMEM>>>(
        hh2, msgh2, 16, 4, wp1, p1_b, p1, nullptr, 0, HID, HID, M_RELU);
    // logits (SIMT fp32)
    gemm8x8<64><<<dim3(1, ROWS / BM), 256>>>(p1, p2_w, p2_b, logits, NACT, NACT, HID, HID);
}

// round 15
// speedup vs baseline: 1.4460x; 1.4460x over previous
#include <cuda_runtime.h>
#include <cuda_fp16.h>
#include <math.h>
#include <stdint.h>

typedef unsigned long long ull;

// ---------------- constants ----------------
#define BS_     2048
#define A_      32
#define ROWS    (BS_ * A_)     // 65536
#define MT_     (ROWS / 128)   // 512 row-blocks
#define IN_DIM  256
#define HID     256
#define NH      4
#define HD      16
#define CV      16
#define TOPK    8
#define NACT    20
#define QKVG_N  196
#define NEGV    (-1e10f)

#define M_NONE    0
#define M_RELU    1
#define M_QKVG    2
#define M_RELU_AF 3

// ---------------- scratch (device globals; no allocation) ----------------
__device__ float g_gi  [ROWS * 3 * HID];
__device__ float g_gh  [ROWS * 3 * HID];
__device__ float g_qkvg[ROWS * QKVG_N];
__device__ float g_p1  [ROWS * HID];
__device__ float g_wq  [QKVG_N * HID];
__device__ float g_bq  [QKVG_N];
// fragment-tiled fp16 hi/lo (uint32 words; block = 2048 words: [hi 1024][lo 1024])
__device__ uint32_t g_in_h2 [MT_ * 16 * 2048];
__device__ uint32_t g_hid_h2[MT_ * 16 * 2048];
__device__ uint32_t g_x_h2  [MT_ * 16 * 2048];
__device__ uint32_t g_h_h2  [MT_ * 16 * 2048];
__device__ uint32_t g_msg_h2[MT_ * 4 * 2048];
__device__ uint32_t g_wfc1_h2[2 * 16 * 2048];
__device__ uint32_t g_wih_h2 [6 * 16 * 2048];
__device__ uint32_t g_whh_h2 [6 * 16 * 2048];
__device__ uint32_t g_wq_h2  [2 * 16 * 2048];
__device__ uint32_t g_wp1_h2 [2 * 20 * 2048];

// ---------------- helpers ----------------
__device__ __forceinline__ float sigmoidf_(float x) { return 1.0f / (1.0f + expf(-x)); }

__device__ __forceinline__ void h2pair(float x, float y, uint32_t& hi, uint32_t& lo) {
    __half hx = __float2half_rn(x), hy = __float2half_rn(y);
    float rx = x - __half2float(hx), ry = y - __half2float(hy);
    __half2 H = __halves2half2(hx, hy);
    __half2 L = __halves2half2(__float2half_rn(rx), __float2half_rn(ry));
    hi = *reinterpret_cast<uint32_t*>(&H);
    lo = *reinterpret_cast<uint32_t*>(&L);
}

__device__ __forceinline__ void mma_f16(float* c, const uint32_t* a, const uint32_t* b) {
    asm volatile(
        "mma.sync.aligned.m16n8k16.row.col.f32.f16.f16.f32 "
        "{%0,%1,%2,%3}, {%4,%5,%6,%7}, {%8,%9}, {%0,%1,%2,%3};"
        : "+f"(c[0]), "+f"(c[1]), "+f"(c[2]), "+f"(c[3])
        : "r"(a[0]), "r"(a[1]), "r"(a[2]), "r"(a[3]), "r"(b[0]), "r"(b[1]));
}

// ---------------- split kernels: fp32 -> fragment-tiled fp16 hi/lo ----------------
// AF: block (mt,kt) = 256 threads: word idx = mf*128 + lane*4 + reg, reg = khalf*2 + rhi;
//   value pair = (A[row][k], A[row][k+1]), row = mt*128 + mf*16 + rhi*8 + gid,
//   k = kt*16 + khalf*8 + tg*2; lane = gid*4 + tg.
__global__ void split_a(const float* __restrict__ src, uint32_t* __restrict__ dst,
                        int K, int total)
{
    int t = blockIdx.x * blockDim.x + threadIdx.x;
    if (t >= total) return;
    int KT = K / 16;
    int li = t & 255, blkid = t >> 8;
    int kt = blkid % KT, mt = blkid / KT;
    int mf = li >> 5, lane = li & 31, gid = lane >> 2, tg = lane & 3;
    int row0 = mt * 128 + mf * 16 + gid;
    int k0 = kt * 16 + tg * 2;
    const float* p = src + (size_t)row0 * K + k0;
    float2 a00 = *(const float2*)(p);            // khalf0 rhi0
    float2 a01 = *(const float2*)(p + 8 * K);    // khalf0 rhi1
    float2 a10 = *(const float2*)(p + 8);        // khalf1 rhi0
    float2 a11 = *(const float2*)(p + 8 * K + 8);
    uint32_t h0,l0,h1,l1,h2_,l2,h3,l3;
    h2pair(a00.x, a00.y, h0, l0); h2pair(a01.x, a01.y, h1, l1);
    h2pair(a10.x, a10.y, h2_, l2); h2pair(a11.x, a11.y, h3, l3);
    size_t blk = (size_t)blkid * 2048;
    int idx = mf * 128 + lane * 4;
    *(uint4*)(dst + blk + idx)        = make_uint4(h0, h1, h2_, h3);
    *(uint4*)(dst + blk + 1024 + idx) = make_uint4(l0, l1, l2, l3);
}

// BF: block (nt,kt) = 512 threads: word idx = nf*64 + lane*2 + khalf.
__global__ void split_w(const float* __restrict__ src, uint32_t* __restrict__ dst,
                        int N, int K, int total)
{
    int t = blockIdx.x * blockDim.x + threadIdx.x;
    if (t >= total) return;
    int KT = K / 16;
    int li = t & 511, blkid = t >> 9;
    int kt = blkid % KT, nt = blkid / KT;
    int nf = li >> 5, lane = li & 31, gid = lane >> 2, tg = lane & 3;
    int n = nt * 128 + nf * 8 + gid;
    int k0 = kt * 16 + tg * 2;
    float2 b0 = make_float2(0.f, 0.f), b1 = b0;
    if (n < N) {
        b0 = *(const float2*)(src + (size_t)n * K + k0);
        b1 = *(const float2*)(src + (size_t)n * K + k0 + 8);
    }
    uint32_t h0,l0,h1,l1;
    h2pair(b0.x, b0.y, h0, l0);
    h2pair(b1.x, b1.y, h1, l1);
    size_t blk = (size_t)blkid * 2048;
    int idx = nf * 64 + lane * 2;
    *(uint2*)(dst + blk + idx)        = make_uint2(h0, h1);
    *(uint2*)(dst + blk + 1024 + idx) = make_uint2(l0, l1);
}

// ---------------- 2xFP16 (3-term) GEMM on pre-split fragment-tiled operands ----------
#define TG_SMEM 32768

__global__ __launch_bounds__(256, 2) void tgemm_h2(
    const uint32_t* __restrict__ afA1, const uint32_t* __restrict__ afA2, int KT1, int KT2,
    const uint32_t* __restrict__ bfB, const float* __restrict__ bias,
    float* __restrict__ C, uint32_t* __restrict__ Caf, int ktc,
    int ldc, int N, int mode)
{
    extern __shared__ uint32_t smw[];

    const int tid = threadIdx.x;
    const int lane = tid & 31;
    const int wid = tid >> 5;
    const int wm = wid & 1;
    const int wn = wid >> 1;
    const int mt = blockIdx.y;
    const int nt = blockIdx.x;
    const int KT = KT1 + KT2;

    const uint32_t* baseA1 = afA1 + (size_t)mt * KT1 * 2048;
    const uint32_t* baseA2 = afA2 + (size_t)mt * KT2 * 2048;
    const uint32_t* baseB  = bfB  + (size_t)nt * KT * 2048;

    float acc[4][4][4];
#pragma unroll
    for (int i = 0; i < 4; i++)
#pragma unroll
        for (int j = 0; j < 4; j++)
#pragma unroll
            for (int r = 0; r < 4; r++) acc[i][j][r] = 0.f;

    uint4 f0, f1, f2, f3;
    auto ldg = [&](int c) {
        const uint32_t* sA = (c < KT1) ? baseA1 + c * 2048 : baseA2 + (c - KT1) * 2048;
        const uint32_t* sB = baseB + c * 2048;
        f0 = *(const uint4*)(sA + tid * 4);
        f1 = *(const uint4*)(sA + 1024 + tid * 4);
        f2 = *(const uint4*)(sB + tid * 4);
        f3 = *(const uint4*)(sB + 1024 + tid * 4);
    };
    auto sts = [&](int buf) {
        uint32_t* s = smw + buf * 4096 + tid * 4;
        *(uint4*)(s)        = f0;
        *(uint4*)(s + 1024) = f1;
        *(uint4*)(s + 2048) = f2;
        *(uint4*)(s + 3072) = f3;
    };

    ldg(0); sts(0);
    __syncthreads();

    for (int c = 0; c < KT; c++) {
        if (c + 1 < KT) ldg(c + 1);

        const uint32_t* sw = smw + (c & 1) * 4096;
        uint32_t bh[4][2], bl[4][2];
#pragma unroll
        for (int j = 0; j < 4; j++) {
            const int nf = wn * 4 + j;
            uint2 vh = *(const uint2*)(sw + 2048 + nf * 64 + lane * 2);
            uint2 vl = *(const uint2*)(sw + 3072 + nf * 64 + lane * 2);
            bh[j][0] = vh.x; bh[j][1] = vh.y;
            bl[j][0] = vl.x; bl[j][1] = vl.y;
        }
#pragma unroll
        for (int i = 0; i < 4; i++) {
            const int mf = wm * 4 + i;
            uint4 vh = *(const uint4*)(sw + mf * 128 + lane * 4);
            uint4 vl = *(const uint4*)(sw + 1024 + mf * 128 + lane * 4);
            uint32_t ah[4] = {vh.x, vh.y, vh.z, vh.w};
            uint32_t al[4] = {vl.x, vl.y, vl.z, vl.w};
#pragma unroll
            for (int j = 0; j < 4; j++) {
                mma_f16(acc[i][j], al, bh[j]);
                mma_f16(acc[i][j], ah, bl[j]);
                mma_f16(acc[i][j], ah, bh[j]);
            }
        }

        if (c + 1 < KT) sts((c + 1) & 1);
        __syncthreads();
    }

    // ---- epilogue ----
    const int gid = lane >> 2;
    const int tig = lane & 3;

    if (mode == M_RELU_AF) {
        // coalesced AF output: thread's acc[i][2jp..2jp+1] = the uint4 at
        // block (mt, nt*8 + wn*2 + jp), idx = mf*128 + lane*4.
#pragma unroll
        for (int i = 0; i < 4; i++) {
            const int mf = wm * 4 + i;
#pragma unroll
            for (int jp = 0; jp < 2; jp++) {
                const int kt = nt * 8 + wn * 2 + jp;
                float vals[2][4];
#pragma unroll
                for (int jj = 0; jj < 2; jj++) {
                    int j = jp * 2 + jj;
                    int col = nt * 128 + wn * 32 + j * 8 + tig * 2;
                    float b0 = bias[col], b1 = bias[col + 1];
                    vals[jj][0] = fmaxf(acc[i][j][0] + b0, 0.f);
                    vals[jj][1] = fmaxf(acc[i][j][1] + b1, 0.f);
                    vals[jj][2] = fmaxf(acc[i][j][2] + b0, 0.f);
                    vals[jj][3] = fmaxf(acc[i][j][3] + b1, 0.f);
                }
                uint32_t h0,l0,h1,l1,h2_,l2,h3,l3;
                h2pair(vals[0][0], vals[0][1], h0, l0);   // khalf0 rhi0 -> reg0
                h2pair(vals[0][2], vals[0][3], h1, l1);   // khalf0 rhi1 -> reg1
                h2pair(vals[1][0], vals[1][1], h2_, l2);  // khalf1 rhi0 -> reg2
                h2pair(vals[1][2], vals[1][3], h3, l3);   // khalf1 rhi1 -> reg3
                size_t blk = ((size_t)mt * ktc + kt) * 2048;
                int idx = mf * 128 + lane * 4;
                *(uint4*)(Caf + blk + idx)        = make_uint4(h0, h1, h2_, h3);
                *(uint4*)(Caf + blk + 1024 + idx) = make_uint4(l0, l1, l2, l3);
            }
        }
        return;
    }

#pragma unroll
    for (int i = 0; i < 4; i++) {
        const int rowl = wm * 64 + i * 16 + gid;
#pragma unroll
        for (int j = 0; j < 4; j++) {
            const int col = nt * 128 + wn * 32 + j * 8 + tig * 2;
            if (col < N) {
                const int row0 = mt * 128 + rowl;
                float b0 = bias[col], b1 = bias[col + 1];
                float v0 = acc[i][j][0] + b0, v1 = acc[i][j][1] + b1;
                float v2 = acc[i][j][2] + b0, v3 = acc[i][j][3] + b1;
                if (mode == M_RELU) {
                    v0 = fmaxf(v0, 0.f); v1 = fmaxf(v1, 0.f);
                    v2 = fmaxf(v2, 0.f); v3 = fmaxf(v3, 0.f);
                } else if (mode == M_QKVG && col >= 192) {
                    v0 = sigmoidf_(v0); v1 = sigmoidf_(v1);
                    v2 = sigmoidf_(v2); v3 = sigmoidf_(v3);
                }
                *(float2*)(C + (size_t)row0 * ldc + col)       = make_float2(v0, v1);
                *(float2*)(C + (size_t)(row0 + 8) * ldc + col) = make_float2(v2, v3);
            }
        }
    }
}

// ---------------- SIMT f32x2 GEMM (p2, N=20) ----------------
__device__ __forceinline__ ull pk2(float x) {
    ull r; asm("mov.b64 %0, {%1, %1};" : "=l"(r) : "f"(x)); return r;
}
__device__ __forceinline__ ull pk(float x, float y) {
    ull r; asm("mov.b64 %0, {%1, %2};" : "=l"(r) : "f"(x), "f"(y)); return r;
}
__device__ __forceinline__ void fma2(ull& d, ull a, ull b) {
    asm("fma.rn.f32x2 %0, %1, %2, %0;" : "+l"(d) : "l"(a), "l"(b));
}
__device__ __forceinline__ void unpk(ull v, float& x, float& y) {
    asm("mov.b64 {%0, %1}, %2;" : "=f"(x), "=f"(y) : "l"(v));
}

#define BM 128
#define BK 16
template<int BN>
__global__ __launch_bounds__(256, 2) void gemm8x8(
    const float* __restrict__ A1, const float* __restrict__ B, const float* __restrict__ bias,
    float* __restrict__ C, int ldc, int N, int K, int lda)
{
    constexpr int TN  = BN / 16;
    constexpr int PAD = 4;
    __shared__ __align__(16) float As[BK][BM + PAD];
    __shared__ __align__(16) float Bs[BK][BN + PAD];

    const int tid = threadIdx.x;
    const int m0 = blockIdx.y * BM;
    const int n0 = blockIdx.x * BN;
    const int tx = tid & 15;
    const int ty = tid >> 4;

    ull acc[8][TN / 2];
#pragma unroll
    for (int i = 0; i < 8; i++)
#pragma unroll
        for (int p = 0; p < TN / 2; p++) acc[i][p] = 0ull;

    for (int k0 = 0; k0 < K; k0 += BK) {
#pragma unroll
        for (int r = 0; r < 2; r++) {
            int e = tid + r * 256;
            int row = e >> 2;
            int kq = (e & 3) * 4;
            float4 v = *(const float4*)(A1 + (size_t)(m0 + row) * lda + k0 + kq);
            As[kq + 0][row] = v.x; As[kq + 1][row] = v.y;
            As[kq + 2][row] = v.z; As[kq + 3][row] = v.w;
        }
#pragma unroll
        for (int r = 0; r < BN / 64; r++) {
            int e = tid + r * 256;
            int col = e >> 2;
            int kq = (e & 3) * 4;
            float4 v = make_float4(0.f, 0.f, 0.f, 0.f);
            if (n0 + col < N) v = *(const float4*)(B + (size_t)(n0 + col) * K + k0 + kq);
            Bs[kq + 0][col] = v.x; Bs[kq + 1][col] = v.y;
            Bs[kq + 2][col] = v.z; Bs[kq + 3][col] = v.w;
        }
        __syncthreads();

#pragma unroll
        for (int kk = 0; kk < BK; kk++) {
            float4 a0 = *(const float4*)&As[kk][ty * 8];
            float4 a1 = *(const float4*)&As[kk][ty * 8 + 4];
            float am[8] = {a0.x, a0.y, a0.z, a0.w, a1.x, a1.y, a1.z, a1.w};
            float bn_[TN];
#pragma unroll
            for (int q = 0; q < TN / 4; q++) {
                float4 b = *(const float4*)&Bs[kk][tx * TN + q * 4];
                bn_[q * 4 + 0] = b.x; bn_[q * 4 + 1] = b.y;
                bn_[q * 4 + 2] = b.z; bn_[q * 4 + 3] = b.w;
            }
            ull bp[TN / 2];
#pragma unroll
            for (int p = 0; p < TN / 2; p++) bp[p] = pk(bn_[2 * p], bn_[2 * p + 1]);
#pragma unroll
            for (int i = 0; i < 8; i++) {
                ull aa = pk2(am[i]);
#pragma unroll
                for (int p = 0; p < TN / 2; p++) fma2(acc[i][p], aa, bp[p]);
            }
        }
        __syncthreads();
    }

#pragma unroll
    for (int i = 0; i < 8; i++) {
        int row = m0 + ty * 8 + i;
        float vals[TN];
#pragma unroll
        for (int p = 0; p < TN / 2; p++) unpk(acc[i][p], vals[2 * p], vals[2 * p + 1]);
#pragma unroll
        for (int j = 0; j < TN; j++) {
            int col = n0 + tx * TN + j;
            if (col < N) C[(size_t)row * ldc + col] = vals[j] + bias[col];
        }
    }
}

// ---------------- pack q/k/v/g (fp32, feeds split_w) ----------------
__global__ void pack_qkvg(const float* __restrict__ qw, const float* __restrict__ qb,
                          const float* __restrict__ kw, const float* __restrict__ kb,
                          const float* __restrict__ vw, const float* __restrict__ vb,
                          const float* __restrict__ gw, const float* __restrict__ gb)
{
    int i = blockIdx.x * blockDim.x + threadIdx.x;
    const int total = QKVG_N * HID;
    if (i < total) {
        int row = i / HID, c = i - row * HID;
        float v;
        if      (row < 64)  v = qw[row * HID + c];
        else if (row < 128) v = kw[(row - 64) * HID + c];
        else if (row < 192) v = vw[(row - 128) * HID + c];
        else                v = gw[(row - 192) * HID + c];
        g_wq[i] = v;
    }
    if (i < QKVG_N) {
        float b;
        if      (i < 64)  b = qb[i];
        else if (i < 128) b = kb[i - 64];
        else if (i < 192) b = vb[i - 128];
        else              b = gb[i - 192];
        g_bq[i] = b;
    }
}

// ---------------- GRU gate fusion (AF-coordinate threads; coalesced AF writes) ------
// thread = (mt, kt, mf, lane): rows {r, r+8}, k pairs {k0,k0+1} and {k0+8,k0+9}.
__global__ void gru_gates(const float* __restrict__ gi, const float* __restrict__ gh,
                          const float* __restrict__ hin, float* __restrict__ hout,
                          uint32_t* __restrict__ haf)
{
    int t = blockIdx.x * blockDim.x + threadIdx.x;
    if (t >= ROWS * (HID / 8)) return;
    int li = t & 255, blkid = t >> 8;
    int kt = blkid & 15, mt = blkid >> 4;
    int mf = li >> 5, lane = li & 31, gid = lane >> 2, tg = lane & 3;
    int r0 = mt * 128 + mf * 16 + gid;
    int k0 = kt * 16 + tg * 2;

    uint32_t hw[4], lw[4];   // reg = khalf*2 + rhi
#pragma unroll
    for (int rhi = 0; rhi < 2; rhi++) {
        int row = r0 + rhi * 8;
        const float* gib = gi + (size_t)row * 768;
        const float* ghb = gh + (size_t)row * 768;
#pragma unroll
        for (int kh = 0; kh < 2; kh++) {
            int c = k0 + kh * 8;
            float2 gir = *(const float2*)(gib + c);
            float2 giz = *(const float2*)(gib + c + 256);
            float2 gin = *(const float2*)(gib + c + 512);
            float2 ghr = *(const float2*)(ghb + c);
            float2 ghz = *(const float2*)(ghb + c + 256);
            float2 ghn = *(const float2*)(ghb + c + 512);
            float2 h0  = *(const float2*)(hin + (size_t)row * HID + c);
            float2 o;
            {
                float r = sigmoidf_(gir.x + ghr.x);
                float z = sigmoidf_(giz.x + ghz.x);
                float n = tanhf(gin.x + r * ghn.x);
                o.x = (1.f - z) * n + z * h0.x;
            }
            {
                float r = sigmoidf_(gir.y + ghr.y);
                float z = sigmoidf_(giz.y + ghz.y);
                float n = tanhf(gin.y + r * ghn.y);
                o.y = (1.f - z) * n + z * h0.y;
            }
            *(float2*)(hout + (size_t)row * HID + c) = o;
            h2pair(o.x, o.y, hw[kh * 2 + rhi], lw[kh * 2 + rhi]);
        }
    }
    size_t blk = (size_t)blkid * 2048;   // blkid = mt*16 + kt
    int idx = mf * 128 + lane * 4;
    *(uint4*)(haf + blk + idx)        = make_uint4(hw[0], hw[1], hw[2], hw[3]);
    *(uint4*)(haf + blk + 1024 + idx) = make_uint4(lw[0], lw[1], lw[2], lw[3]);
}

// ---------------- per-batch sparse attention (writes msg_h2 AF, KT=4) ------------
__global__ __launch_bounds__(128) void attention_kernel(const float* __restrict__ qkvg,
                                                        uint32_t* __restrict__ msgaf)
{
    __shared__ float q_s[A_][64];
    __shared__ float k_s[A_][64];
    __shared__ float v_s[A_][64];
    __shared__ float g_s[A_][NH];

    const int b = blockIdx.x;
    const int tid = threadIdx.x;
    const float* base = qkvg + (size_t)b * A_ * QKVG_N;

    for (int idx = tid; idx < A_ * QKVG_N; idx += 128) {
        int r = idx / QKVG_N, c = idx - r * QKVG_N;
        float v = base[(size_t)r * QKVG_N + c];
        if      (c < 64)  q_s[r][c] = v;
        else if (c < 128) k_s[r][c - 64] = v;
        else if (c < 192) v_s[r][c - 128] = v;
        else              g_s[r][c - 192] = v;
    }
    __syncthreads();

    const int qa = tid >> 2;
    const int hh = tid & 3;
    const int hb = hh * HD;

    float qv[HD];
#pragma unroll
    for (int d = 0; d < HD; d++) qv[d] = q_s[qa][hb + d];

    float sc[A_];
#pragma unroll
    for (int ka = 0; ka < A_; ka++) {
        float s = 0.f;
#pragma unroll
        for (int d = 0; d < HD; d++) s += qv[d] * k_s[ka][hb + d];
        sc[ka] = (ka == qa) ? NEGV : s * 0.25f;
    }

    unsigned sel = 0;
    float maxv = NEGV;
    for (int it = 0; it < TOPK; it++) {
        float best = -INFINITY; int bi = 0;
#pragma unroll
        for (int ka = 0; ka < A_; ka++) {
            bool free_ = !((sel >> ka) & 1u);
            if (free_ && sc[ka] > best) { best = sc[ka]; bi = ka; }
        }
        sel |= (1u << bi);
        if (it == 0) maxv = best;
    }

    float sum = 0.f;
#pragma unroll
    for (int ka = 0; ka < A_; ka++) {
        float e = ((sel >> ka) & 1u) ? expf(sc[ka] - maxv) : 0.f;
        sc[ka] = e;
        sum += e;
    }
    float inv = 1.f / sum;

    float m[CV];
#pragma unroll
    for (int d = 0; d < CV; d++) m[d] = 0.f;
#pragma unroll
    for (int ka = 0; ka < A_; ka++) {
        float w = sc[ka];
#pragma unroll
        for (int d = 0; d < CV; d++) m[d] += w * v_s[ka][hb + d];
    }

    float gate = g_s[qa][hh];
    float scale = inv * gate;

    const int row = b * A_ + qa;
    int mt = row >> 7, rl = row & 127, mf = rl >> 4, rr = rl & 15;
    int gid8 = rr & 7, rhi = rr >> 3;
    size_t blk = ((size_t)mt * 4 + hh) * 2048;
#pragma unroll
    for (int p = 0; p < 8; p++) {
        int khalf = p >> 2, tg = p & 3;
        int idx = mf * 128 + (gid8 * 4 + tg) * 4 + khalf * 2 + rhi;
        uint32_t h, l;
        h2pair(m[2 * p] * scale, m[2 * p + 1] * scale, h, l);
        msgaf[blk + idx] = h;
        msgaf[blk + 1024 + idx] = l;
    }
}

// ---------------- launch ----------------
extern "C" void kernel_launch(void* const* d_in, const int* in_sizes, int n_in,
                              void* d_out, int out_size)
{
    const float* inputs = (const float*)d_in[0];
    const float* hidden = (const float*)d_in[1];
    const float* fc1_w  = (const float*)d_in[2];
    const float* fc1_b  = (const float*)d_in[3];
    const float* w_ih   = (const float*)d_in[4];
    const float* w_hh   = (const float*)d_in[5];
    const float* b_ih   = (const float*)d_in[6];
    const float* b_hh   = (const float*)d_in[7];
    const float* q_w    = (const float*)d_in[8];
    const float* q_b    = (const float*)d_in[9];
    const float* k_w    = (const float*)d_in[10];
    const float* k_b    = (const float*)d_in[11];
    const float* v_w    = (const float*)d_in[12];
    const float* v_b    = (const float*)d_in[13];
    const float* g_w    = (const float*)d_in[14];
    const float* g_b    = (const float*)d_in[15];
    const float* p1_w   = (const float*)d_in[16];
    const float* p1_b   = (const float*)d_in[17];
    const float* p2_w   = (const float*)d_in[18];
    const float* p2_b   = (const float*)d_in[19];

    float* out    = (float*)d_out;
    float* logits = out;                       // [65536, 20]
    float* hout   = out + (size_t)ROWS * NACT; // [65536, 256]

    float *gi, *gh, *qkvg, *p1, *wq, *bq;
    uint32_t *inh2, *hidh2, *xh2, *hh2, *msgh2, *wfc1, *wih, *whh, *wq2, *wp1;
    cudaGetSymbolAddress((void**)&gi,    g_gi);
    cudaGetSymbolAddress((void**)&gh,    g_gh);
    cudaGetSymbolAddress((void**)&qkvg,  g_qkvg);
    cudaGetSymbolAddress((void**)&p1,    g_p1);
    cudaGetSymbolAddress((void**)&wq,    g_wq);
    cudaGetSymbolAddress((void**)&bq,    g_bq);
    cudaGetSymbolAddress((void**)&inh2,  g_in_h2);
    cudaGetSymbolAddress((void**)&hidh2, g_hid_h2);
    cudaGetSymbolAddress((void**)&xh2,   g_x_h2);
    cudaGetSymbolAddress((void**)&hh2,   g_h_h2);
    cudaGetSymbolAddress((void**)&msgh2, g_msg_h2);
    cudaGetSymbolAddress((void**)&wfc1,  g_wfc1_h2);
    cudaGetSymbolAddress((void**)&wih,   g_wih_h2);
    cudaGetSymbolAddress((void**)&whh,   g_whh_h2);
    cudaGetSymbolAddress((void**)&wq2,   g_wq_h2);
    cudaGetSymbolAddress((void**)&wp1,   g_wp1_h2);

    const int MYT = MT_;   // 512

    // weight packs/splits (tiny)
    pack_qkvg<<<(QKVG_N * HID + 255) / 256, 256>>>(q_w, q_b, k_w, k_b, v_w, v_b, g_w, g_b);
    {
        int t1 = 2 * 16 * 512;
        int t2 = 6 * 16 * 512;
        int t3 = 2 * 20 * 512;
        split_w<<<(t1 + 255) / 256, 256>>>(fc1_w, wfc1, HID, IN_DIM, t1);
        split_w<<<(t2 + 255) / 256, 256>>>(w_ih, wih, 3 * HID, HID, t2);
        split_w<<<(t2 + 255) / 256, 256>>>(w_hh, whh, 3 * HID, HID, t2);
        split_w<<<(t1 + 255) / 256, 256>>>(wq, wq2, QKVG_N, HID, t1);
        split_w<<<(t3 + 255) / 256, 256>>>(p1_w, wp1, HID, HID + NH * CV, t3);
    }
    // input splits (256 threads per AF block)
    {
        int ta = MT_ * 16 * 256;
        split_a<<<(ta + 255) / 256, 256>>>(inputs, inh2, IN_DIM, ta);
        split_a<<<(ta + 255) / 256, 256>>>(hidden, hidh2, HID, ta);
    }

    // x = relu(fc1) -> x_h2 (AF, KT=16)
    tgemm_h2<<<dim3(2, MYT), 256, TG_SMEM>>>(
        inh2, inh2, 16, 0, wfc1, fc1_b, nullptr, xh2, 16, 0, HID, M_RELU_AF);
    // gi / gh (fp32)
    tgemm_h2<<<dim3(6, MYT), 256, TG_SMEM>>>(
        xh2, xh2, 16, 0, wih, b_ih, gi, nullptr, 0, 3 * HID, 3 * HID, M_NONE);
    tgemm_h2<<<dim3(6, MYT), 256, TG_SMEM>>>(
        hidh2, hidh2, 16, 0, whh, b_hh, gh, nullptr, 0, 3 * HID, 3 * HID, M_NONE);
    // h (fp32 out + coalesced AF)
    gru_gates<<<(ROWS * (HID / 8) + 255) / 256, 256>>>(gi, gh, hidden, hout, hh2);
    // qkvg (fp32, sigmoid on gate cols)
    tgemm_h2<<<dim3(2, MYT), 256, TG_SMEM>>>(
        hh2, hh2, 16, 0, wq2, bq, qkvg, nullptr, 0, QKVG_N, QKVG_N, M_QKVG);
    // attention -> msg_h2 (AF, KT=4)
    attention_kernel<<<BS_, 128>>>(qkvg, msgh2);
    // p1 = relu([h | msg] @ p1_w^T + b)  (split-A: 16 + 4 chunks)
    tgemm_h2<<<dim3(2, MYT), 256, TG_SMEM>>>(
        hh2, msgh2, 16, 4, wp1, p1_b, p1, nullptr, 0, HID, HID, M_RELU);
    // logits (SIMT fp32)
    gemm8x8<64><<<dim3(1, ROWS / BM), 256>>>(p1, p2_w, p2_b, logits, NACT, NACT, HID, HID);
}

// round 16
// speedup vs baseline: 1.4926x; 1.0322x over previous
#include <cuda_runtime.h>
#include <cuda_fp16.h>
#include <math.h>
#include <stdint.h>

typedef unsigned long long ull;

// ---------------- constants ----------------
#define BS_     2048
#define A_      32
#define ROWS    (BS_ * A_)     // 65536
#define MT_     (ROWS / 128)   // 512 row-blocks
#define IN_DIM  256
#define HID     256
#define NH      4
#define HD      16
#define CV      16
#define TOPK    8
#define NACT    20
#define QKVG_N  196
#define NEGV    (-1e10f)

#define M_NONE    0
#define M_RELU    1
#define M_QKVG    2
#define M_RELU_AF 3

// ---------------- scratch (device globals; no allocation) ----------------
__device__ float g_gi  [ROWS * 3 * HID];
__device__ float g_gh  [ROWS * 3 * HID];
__device__ float g_qkvg[ROWS * QKVG_N];
__device__ float g_p1  [ROWS * HID];
__device__ float g_wq  [QKVG_N * HID];
__device__ float g_bq  [QKVG_N];
// fragment-tiled fp16 hi/lo (uint32 words; block = 2048 words: [hi 1024][lo 1024])
__device__ uint32_t g_in_h2 [MT_ * 16 * 2048];
__device__ uint32_t g_hid_h2[MT_ * 16 * 2048];
__device__ uint32_t g_x_h2  [MT_ * 16 * 2048];
__device__ uint32_t g_h_h2  [MT_ * 16 * 2048];
__device__ uint32_t g_msg_h2[MT_ * 4 * 2048];
__device__ uint32_t g_wfc1_h2[2 * 16 * 2048];
__device__ uint32_t g_wih_h2 [6 * 16 * 2048];
__device__ uint32_t g_whh_h2 [6 * 16 * 2048];
__device__ uint32_t g_wq_h2  [2 * 16 * 2048];
__device__ uint32_t g_wp1_h2 [2 * 20 * 2048];

// ---------------- helpers ----------------
__device__ __forceinline__ float sigmoidf_(float x) { return 1.0f / (1.0f + expf(-x)); }

__device__ __forceinline__ void h2pair(float x, float y, uint32_t& hi, uint32_t& lo) {
    __half hx = __float2half_rn(x), hy = __float2half_rn(y);
    float rx = x - __half2float(hx), ry = y - __half2float(hy);
    __half2 H = __halves2half2(hx, hy);
    __half2 L = __halves2half2(__float2half_rn(rx), __float2half_rn(ry));
    hi = *reinterpret_cast<uint32_t*>(&H);
    lo = *reinterpret_cast<uint32_t*>(&L);
}

__device__ __forceinline__ void mma_f16(float* c, const uint32_t* a, const uint32_t* b) {
    asm volatile(
        "mma.sync.aligned.m16n8k16.row.col.f32.f16.f16.f32 "
        "{%0,%1,%2,%3}, {%4,%5,%6,%7}, {%8,%9}, {%0,%1,%2,%3};"
        : "+f"(c[0]), "+f"(c[1]), "+f"(c[2]), "+f"(c[3])
        : "r"(a[0]), "r"(a[1]), "r"(a[2]), "r"(a[3]), "r"(b[0]), "r"(b[1]));
}

__device__ __forceinline__ void cp16(uint32_t smaddr, const void* gptr) {
    asm volatile("cp.async.cg.shared.global [%0], [%1], 16;"
                 :: "r"(smaddr), "l"(gptr) : "memory");
}
__device__ __forceinline__ void cp_commit() {
    asm volatile("cp.async.commit_group;" ::: "memory");
}
__device__ __forceinline__ void cp_wait2() {
    asm volatile("cp.async.wait_group 2;" ::: "memory");
}

// ---------------- split kernels: fp32 -> fragment-tiled fp16 hi/lo ----------------
__global__ void split_a(const float* __restrict__ src, uint32_t* __restrict__ dst,
                        int K, int total)
{
    int t = blockIdx.x * blockDim.x + threadIdx.x;
    if (t >= total) return;
    int KT = K / 16;
    int li = t & 255, blkid = t >> 8;
    int kt = blkid % KT, mt = blkid / KT;
    int mf = li >> 5, lane = li & 31, gid = lane >> 2, tg = lane & 3;
    int row0 = mt * 128 + mf * 16 + gid;
    int k0 = kt * 16 + tg * 2;
    const float* p = src + (size_t)row0 * K + k0;
    float2 a00 = *(const float2*)(p);
    float2 a01 = *(const float2*)(p + 8 * K);
    float2 a10 = *(const float2*)(p + 8);
    float2 a11 = *(const float2*)(p + 8 * K + 8);
    uint32_t h0,l0,h1,l1,h2_,l2,h3,l3;
    h2pair(a00.x, a00.y, h0, l0); h2pair(a01.x, a01.y, h1, l1);
    h2pair(a10.x, a10.y, h2_, l2); h2pair(a11.x, a11.y, h3, l3);
    size_t blk = (size_t)blkid * 2048;
    int idx = mf * 128 + lane * 4;
    *(uint4*)(dst + blk + idx)        = make_uint4(h0, h1, h2_, h3);
    *(uint4*)(dst + blk + 1024 + idx) = make_uint4(l0, l1, l2, l3);
}

__global__ void split_w(const float* __restrict__ src, uint32_t* __restrict__ dst,
                        int N, int K, int total)
{
    int t = blockIdx.x * blockDim.x + threadIdx.x;
    if (t >= total) return;
    int KT = K / 16;
    int li = t & 511, blkid = t >> 9;
    int kt = blkid % KT, nt = blkid / KT;
    int nf = li >> 5, lane = li & 31, gid = lane >> 2, tg = lane & 3;
    int n = nt * 128 + nf * 8 + gid;
    int k0 = kt * 16 + tg * 2;
    float2 b0 = make_float2(0.f, 0.f), b1 = b0;
    if (n < N) {
        b0 = *(const float2*)(src + (size_t)n * K + k0);
        b1 = *(const float2*)(src + (size_t)n * K + k0 + 8);
    }
    uint32_t h0,l0,h1,l1;
    h2pair(b0.x, b0.y, h0, l0);
    h2pair(b1.x, b1.y, h1, l1);
    size_t blk = (size_t)blkid * 2048;
    int idx = nf * 64 + lane * 2;
    *(uint2*)(dst + blk + idx)        = make_uint2(h0, h1);
    *(uint2*)(dst + blk + 1024 + idx) = make_uint2(l0, l1);
}

// ---------------- 2xFP16 (3-term) GEMM, cp.async 4-stage pipeline ----------------
// Stage = 4096 words (16KB): [A_hi 1024][A_lo 1024][B_hi 1024][B_lo 1024]; 4 stages = 64KB.
#define TG_STAGES 4
#define TG_SMEM   (TG_STAGES * 4096 * 4)

__global__ __launch_bounds__(256, 2) void tgemm_h2(
    const uint32_t* __restrict__ afA1, const uint32_t* __restrict__ afA2, int KT1, int KT2,
    const uint32_t* __restrict__ bfB, const float* __restrict__ bias,
    float* __restrict__ C, uint32_t* __restrict__ Caf, int ktc,
    int ldc, int N, int mode)
{
    extern __shared__ uint32_t smw[];
    const uint32_t smbase = (uint32_t)__cvta_generic_to_shared(smw);

    const int tid = threadIdx.x;
    const int lane = tid & 31;
    const int wid = tid >> 5;
    const int wm = wid & 1;
    const int wn = wid >> 1;
    const int mt = blockIdx.y;
    const int nt = blockIdx.x;
    const int KT = KT1 + KT2;

    const uint32_t* baseA1 = afA1 + (size_t)mt * KT1 * 2048;
    const uint32_t* baseA2 = afA2 + (size_t)mt * KT2 * 2048;
    const uint32_t* baseB  = bfB  + (size_t)nt * KT * 2048;

    float acc[4][4][4];
#pragma unroll
    for (int i = 0; i < 4; i++)
#pragma unroll
        for (int j = 0; j < 4; j++)
#pragma unroll
            for (int r = 0; r < 4; r++) acc[i][j][r] = 0.f;

    auto issue = [&](int c) {
        const uint32_t* sA = (c < KT1) ? baseA1 + c * 2048 : baseA2 + (c - KT1) * 2048;
        const uint32_t* sB = baseB + c * 2048;
        uint32_t dst = smbase + ((c & (TG_STAGES - 1)) * 4096 + tid * 4) * 4;
        cp16(dst,         sA + tid * 4);
        cp16(dst + 4096,  sA + 1024 + tid * 4);
        cp16(dst + 8192,  sB + tid * 4);
        cp16(dst + 12288, sB + 1024 + tid * 4);
        cp_commit();
    };

#pragma unroll
    for (int s = 0; s < TG_STAGES - 1; s++)
        if (s < KT) issue(s);

    for (int c = 0; c < KT; c++) {
        cp_wait2();
        __syncthreads();
        if (c + TG_STAGES - 1 < KT) issue(c + TG_STAGES - 1);

        const uint32_t* sw = smw + (c & (TG_STAGES - 1)) * 4096;
        uint32_t bh[4][2], bl[4][2];
#pragma unroll
        for (int j = 0; j < 4; j++) {
            const int nf = wn * 4 + j;
            uint2 vh = *(const uint2*)(sw + 2048 + nf * 64 + lane * 2);
            uint2 vl = *(const uint2*)(sw + 3072 + nf * 64 + lane * 2);
            bh[j][0] = vh.x; bh[j][1] = vh.y;
            bl[j][0] = vl.x; bl[j][1] = vl.y;
        }
#pragma unroll
        for (int i = 0; i < 4; i++) {
            const int mf = wm * 4 + i;
            uint4 vh = *(const uint4*)(sw + mf * 128 + lane * 4);
            uint4 vl = *(const uint4*)(sw + 1024 + mf * 128 + lane * 4);
            uint32_t ah[4] = {vh.x, vh.y, vh.z, vh.w};
            uint32_t al[4] = {vl.x, vl.y, vl.z, vl.w};
#pragma unroll
            for (int j = 0; j < 4; j++) {
                mma_f16(acc[i][j], al, bh[j]);
                mma_f16(acc[i][j], ah, bl[j]);
                mma_f16(acc[i][j], ah, bh[j]);
            }
        }
        __syncthreads();
    }

    // ---- epilogue ----
    const int gid = lane >> 2;
    const int tig = lane & 3;

    if (mode == M_RELU_AF) {
#pragma unroll
        for (int i = 0; i < 4; i++) {
            const int mf = wm * 4 + i;
#pragma unroll
            for (int jp = 0; jp < 2; jp++) {
                const int kt = nt * 8 + wn * 2 + jp;
                float vals[2][4];
#pragma unroll
                for (int jj = 0; jj < 2; jj++) {
                    int j = jp * 2 + jj;
                    int col = nt * 128 + wn * 32 + j * 8 + tig * 2;
                    float b0 = bias[col], b1 = bias[col + 1];
                    vals[jj][0] = fmaxf(acc[i][j][0] + b0, 0.f);
                    vals[jj][1] = fmaxf(acc[i][j][1] + b1, 0.f);
                    vals[jj][2] = fmaxf(acc[i][j][2] + b0, 0.f);
                    vals[jj][3] = fmaxf(acc[i][j][3] + b1, 0.f);
                }
                uint32_t h0,l0,h1,l1,h2_,l2,h3,l3;
                h2pair(vals[0][0], vals[0][1], h0, l0);
                h2pair(vals[0][2], vals[0][3], h1, l1);
                h2pair(vals[1][0], vals[1][1], h2_, l2);
                h2pair(vals[1][2], vals[1][3], h3, l3);
                size_t blk = ((size_t)mt * ktc + kt) * 2048;
                int idx = mf * 128 + lane * 4;
                *(uint4*)(Caf + blk + idx)        = make_uint4(h0, h1, h2_, h3);
                *(uint4*)(Caf + blk + 1024 + idx) = make_uint4(l0, l1, l2, l3);
            }
        }
        return;
    }

#pragma unroll
    for (int i = 0; i < 4; i++) {
        const int rowl = wm * 64 + i * 16 + gid;
#pragma unroll
        for (int j = 0; j < 4; j++) {
            const int col = nt * 128 + wn * 32 + j * 8 + tig * 2;
            if (col < N) {
                const int row0 = mt * 128 + rowl;
                float b0 = bias[col], b1 = bias[col + 1];
                float v0 = acc[i][j][0] + b0, v1 = acc[i][j][1] + b1;
                float v2 = acc[i][j][2] + b0, v3 = acc[i][j][3] + b1;
                if (mode == M_RELU) {
                    v0 = fmaxf(v0, 0.f); v1 = fmaxf(v1, 0.f);
                    v2 = fmaxf(v2, 0.f); v3 = fmaxf(v3, 0.f);
                } else if (mode == M_QKVG && col >= 192) {
                    v0 = sigmoidf_(v0); v1 = sigmoidf_(v1);
                    v2 = sigmoidf_(v2); v3 = sigmoidf_(v3);
                }
                *(float2*)(C + (size_t)row0 * ldc + col)       = make_float2(v0, v1);
                *(float2*)(C + (size_t)(row0 + 8) * ldc + col) = make_float2(v2, v3);
            }
        }
    }
}

// ---------------- SIMT f32x2 GEMM (p2, N=20) ----------------
__device__ __forceinline__ ull pk2(float x) {
    ull r; asm("mov.b64 %0, {%1, %1};" : "=l"(r) : "f"(x)); return r;
}
__device__ __forceinline__ ull pk(float x, float y) {
    ull r; asm("mov.b64 %0, {%1, %2};" : "=l"(r) : "f"(x), "f"(y)); return r;
}
__device__ __forceinline__ void fma2(ull& d, ull a, ull b) {
    asm("fma.rn.f32x2 %0, %1, %2, %0;" : "+l"(d) : "l"(a), "l"(b));
}
__device__ __forceinline__ void unpk(ull v, float& x, float& y) {
    asm("mov.b64 {%0, %1}, %2;" : "=f"(x), "=f"(y) : "l"(v));
}

#define BM 128
#define BK 16
template<int BN>
__global__ __launch_bounds__(256, 2) void gemm8x8(
    const float* __restrict__ A1, const float* __restrict__ B, const float* __restrict__ bias,
    float* __restrict__ C, int ldc, int N, int K, int lda)
{
    constexpr int TN  = BN / 16;
    constexpr int PAD = 4;
    __shared__ __align__(16) float As[BK][BM + PAD];
    __shared__ __align__(16) float Bs[BK][BN + PAD];

    const int tid = threadIdx.x;
    const int m0 = blockIdx.y * BM;
    const int n0 = blockIdx.x * BN;
    const int tx = tid & 15;
    const int ty = tid >> 4;

    ull acc[8][TN / 2];
#pragma unroll
    for (int i = 0; i < 8; i++)
#pragma unroll
        for (int p = 0; p < TN / 2; p++) acc[i][p] = 0ull;

    for (int k0 = 0; k0 < K; k0 += BK) {
#pragma unroll
        for (int r = 0; r < 2; r++) {
            int e = tid + r * 256;
            int row = e >> 2;
            int kq = (e & 3) * 4;
            float4 v = *(const float4*)(A1 + (size_t)(m0 + row) * lda + k0 + kq);
            As[kq + 0][row] = v.x; As[kq + 1][row] = v.y;
            As[kq + 2][row] = v.z; As[kq + 3][row] = v.w;
        }
#pragma unroll
        for (int r = 0; r < BN / 64; r++) {
            int e = tid + r * 256;
            int col = e >> 2;
            int kq = (e & 3) * 4;
            float4 v = make_float4(0.f, 0.f, 0.f, 0.f);
            if (n0 + col < N) v = *(const float4*)(B + (size_t)(n0 + col) * K + k0 + kq);
            Bs[kq + 0][col] = v.x; Bs[kq + 1][col] = v.y;
            Bs[kq + 2][col] = v.z; Bs[kq + 3][col] = v.w;
        }
        __syncthreads();

#pragma unroll
        for (int kk = 0; kk < BK; kk++) {
            float4 a0 = *(const float4*)&As[kk][ty * 8];
            float4 a1 = *(const float4*)&As[kk][ty * 8 + 4];
            float am[8] = {a0.x, a0.y, a0.z, a0.w, a1.x, a1.y, a1.z, a1.w};
            float bn_[TN];
#pragma unroll
            for (int q = 0; q < TN / 4; q++) {
                float4 b = *(const float4*)&Bs[kk][tx * TN + q * 4];
                bn_[q * 4 + 0] = b.x; bn_[q * 4 + 1] = b.y;
                bn_[q * 4 + 2] = b.z; bn_[q * 4 + 3] = b.w;
            }
            ull bp[TN / 2];
#pragma unroll
            for (int p = 0; p < TN / 2; p++) bp[p] = pk(bn_[2 * p], bn_[2 * p + 1]);
#pragma unroll
            for (int i = 0; i < 8; i++) {
                ull aa = pk2(am[i]);
#pragma unroll
                for (int p = 0; p < TN / 2; p++) fma2(acc[i][p], aa, bp[p]);
            }
        }
        __syncthreads();
    }

#pragma unroll
    for (int i = 0; i < 8; i++) {
        int row = m0 + ty * 8 + i;
        float vals[TN];
#pragma unroll
        for (int p = 0; p < TN / 2; p++) unpk(acc[i][p], vals[2 * p], vals[2 * p + 1]);
#pragma unroll
        for (int j = 0; j < TN; j++) {
            int col = n0 + tx * TN + j;
            if (col < N) C[(size_t)row * ldc + col] = vals[j] + bias[col];
        }
    }
}

// ---------------- pack q/k/v/g ----------------
__global__ void pack_qkvg(const float* __restrict__ qw, const float* __restrict__ qb,
                          const float* __restrict__ kw, const float* __restrict__ kb,
                          const float* __restrict__ vw, const float* __restrict__ vb,
                          const float* __restrict__ gw, const float* __restrict__ gb)
{
    int i = blockIdx.x * blockDim.x + threadIdx.x;
    const int total = QKVG_N * HID;
    if (i < total) {
        int row = i / HID, c = i - row * HID;
        float v;
        if      (row < 64)  v = qw[row * HID + c];
        else if (row < 128) v = kw[(row - 64) * HID + c];
        else if (row < 192) v = vw[(row - 128) * HID + c];
        else                v = gw[(row - 192) * HID + c];
        g_wq[i] = v;
    }
    if (i < QKVG_N) {
        float b;
        if      (i < 64)  b = qb[i];
        else if (i < 128) b = kb[i - 64];
        else if (i < 192) b = vb[i - 128];
        else              b = gb[i - 192];
        g_bq[i] = b;
    }
}

// ---------------- GRU gate fusion (AF-coordinate threads; coalesced AF writes) ------
__global__ void gru_gates(const float* __restrict__ gi, const float* __restrict__ gh,
                          const float* __restrict__ hin, float* __restrict__ hout,
                          uint32_t* __restrict__ haf)
{
    int t = blockIdx.x * blockDim.x + threadIdx.x;
    if (t >= ROWS * (HID / 8)) return;
    int li = t & 255, blkid = t >> 8;
    int kt = blkid & 15, mt = blkid >> 4;
    int mf = li >> 5, lane = li & 31, gid = lane >> 2, tg = lane & 3;
    int r0 = mt * 128 + mf * 16 + gid;
    int k0 = kt * 16 + tg * 2;

    uint32_t hw[4], lw[4];
#pragma unroll
    for (int rhi = 0; rhi < 2; rhi++) {
        int row = r0 + rhi * 8;
        const float* gib = gi + (size_t)row * 768;
        const float* ghb = gh + (size_t)row * 768;
#pragma unroll
        for (int kh = 0; kh < 2; kh++) {
            int c = k0 + kh * 8;
            float2 gir = *(const float2*)(gib + c);
            float2 giz = *(const float2*)(gib + c + 256);
            float2 gin = *(const float2*)(gib + c + 512);
            float2 ghr = *(const float2*)(ghb + c);
            float2 ghz = *(const float2*)(ghb + c + 256);
            float2 ghn = *(const float2*)(ghb + c + 512);
            float2 h0  = *(const float2*)(hin + (size_t)row * HID + c);
            float2 o;
            {
                float r = sigmoidf_(gir.x + ghr.x);
                float z = sigmoidf_(giz.x + ghz.x);
                float n = tanhf(gin.x + r * ghn.x);
                o.x = (1.f - z) * n + z * h0.x;
            }
            {
                float r = sigmoidf_(gir.y + ghr.y);
                float z = sigmoidf_(giz.y + ghz.y);
                float n = tanhf(gin.y + r * ghn.y);
                o.y = (1.f - z) * n + z * h0.y;
            }
            *(float2*)(hout + (size_t)row * HID + c) = o;
            h2pair(o.x, o.y, hw[kh * 2 + rhi], lw[kh * 2 + rhi]);
        }
    }
    size_t blk = (size_t)blkid * 2048;
    int idx = mf * 128 + lane * 4;
    *(uint4*)(haf + blk + idx)        = make_uint4(hw[0], hw[1], hw[2], hw[3]);
    *(uint4*)(haf + blk + 1024 + idx) = make_uint4(lw[0], lw[1], lw[2], lw[3]);
}

// ---------------- per-batch sparse attention (writes msg_h2 AF, KT=4) ------------
__global__ __launch_bounds__(128) void attention_kernel(const float* __restrict__ qkvg,
                                                        uint32_t* __restrict__ msgaf)
{
    __shared__ float q_s[A_][64];
    __shared__ float k_s[A_][64];
    __shared__ float v_s[A_][64];
    __shared__ float g_s[A_][NH];

    const int b = blockIdx.x;
    const int tid = threadIdx.x;
    const float* base = qkvg + (size_t)b * A_ * QKVG_N;

    for (int idx = tid; idx < A_ * QKVG_N; idx += 128) {
        int r = idx / QKVG_N, c = idx - r * QKVG_N;
        float v = base[(size_t)r * QKVG_N + c];
        if      (c < 64)  q_s[r][c] = v;
        else if (c < 128) k_s[r][c - 64] = v;
        else if (c < 192) v_s[r][c - 128] = v;
        else              g_s[r][c - 192] = v;
    }
    __syncthreads();

    const int qa = tid >> 2;
    const int hh = tid & 3;
    const int hb = hh * HD;

    float qv[HD];
#pragma unroll
    for (int d = 0; d < HD; d++) qv[d] = q_s[qa][hb + d];

    float sc[A_];
#pragma unroll
    for (int ka = 0; ka < A_; ka++) {
        float s = 0.f;
#pragma unroll
        for (int d = 0; d < HD; d++) s += qv[d] * k_s[ka][hb + d];
        sc[ka] = (ka == qa) ? NEGV : s * 0.25f;
    }

    unsigned sel = 0;
    float maxv = NEGV;
    for (int it = 0; it < TOPK; it++) {
        float best = -INFINITY; int bi = 0;
#pragma unroll
        for (int ka = 0; ka < A_; ka++) {
            bool free_ = !((sel >> ka) & 1u);
            if (free_ && sc[ka] > best) { best = sc[ka]; bi = ka; }
        }
        sel |= (1u << bi);
        if (it == 0) maxv = best;
    }

    float sum = 0.f;
#pragma unroll
    for (int ka = 0; ka < A_; ka++) {
        float e = ((sel >> ka) & 1u) ? expf(sc[ka] - maxv) : 0.f;
        sc[ka] = e;
        sum += e;
    }
    float inv = 1.f / sum;

    float m[CV];
#pragma unroll
    for (int d = 0; d < CV; d++) m[d] = 0.f;
#pragma unroll
    for (int ka = 0; ka < A_; ka++) {
        float w = sc[ka];
#pragma unroll
        for (int d = 0; d < CV; d++) m[d] += w * v_s[ka][hb + d];
    }

    float gate = g_s[qa][hh];
    float scale = inv * gate;

    const int row = b * A_ + qa;
    int mt = row >> 7, rl = row & 127, mf = rl >> 4, rr = rl & 15;
    int gid8 = rr & 7, rhi = rr >> 3;
    size_t blk = ((size_t)mt * 4 + hh) * 2048;
#pragma unroll
    for (int p = 0; p < 8; p++) {
        int khalf = p >> 2, tg = p & 3;
        int idx = mf * 128 + (gid8 * 4 + tg) * 4 + khalf * 2 + rhi;
        uint32_t h, l;
        h2pair(m[2 * p] * scale, m[2 * p + 1] * scale, h, l);
        msgaf[blk + idx] = h;
        msgaf[blk + 1024 + idx] = l;
    }
}

// ---------------- launch ----------------
extern "C" void kernel_launch(void* const* d_in, const int* in_sizes, int n_in,
                              void* d_out, int out_size)
{
    const float* inputs = (const float*)d_in[0];
    const float* hidden = (const float*)d_in[1];
    const float* fc1_w  = (const float*)d_in[2];
    const float* fc1_b  = (const float*)d_in[3];
    const float* w_ih   = (const float*)d_in[4];
    const float* w_hh   = (const float*)d_in[5];
    const float* b_ih   = (const float*)d_in[6];
    const float* b_hh   = (const float*)d_in[7];
    const float* q_w    = (const float*)d_in[8];
    const float* q_b    = (const float*)d_in[9];
    const float* k_w    = (const float*)d_in[10];
    const float* k_b    = (const float*)d_in[11];
    const float* v_w    = (const float*)d_in[12];
    const float* v_b    = (const float*)d_in[13];
    const float* g_w    = (const float*)d_in[14];
    const float* g_b    = (const float*)d_in[15];
    const float* p1_w   = (const float*)d_in[16];
    const float* p1_b   = (const float*)d_in[17];
    const float* p2_w   = (const float*)d_in[18];
    const float* p2_b   = (const float*)d_in[19];

    float* out    = (float*)d_out;
    float* logits = out;                       // [65536, 20]
    float* hout   = out + (size_t)ROWS * NACT; // [65536, 256]

    float *gi, *gh, *qkvg, *p1, *wq, *bq;
    uint32_t *inh2, *hidh2, *xh2, *hh2, *msgh2, *wfc1, *wih, *whh, *wq2, *wp1;
    cudaGetSymbolAddress((void**)&gi,    g_gi);
    cudaGetSymbolAddress((void**)&gh,    g_gh);
    cudaGetSymbolAddress((void**)&qkvg,  g_qkvg);
    cudaGetSymbolAddress((void**)&p1,    g_p1);
    cudaGetSymbolAddress((void**)&wq,    g_wq);
    cudaGetSymbolAddress((void**)&bq,    g_bq);
    cudaGetSymbolAddress((void**)&inh2,  g_in_h2);
    cudaGetSymbolAddress((void**)&hidh2, g_hid_h2);
    cudaGetSymbolAddress((void**)&xh2,   g_x_h2);
    cudaGetSymbolAddress((void**)&hh2,   g_h_h2);
    cudaGetSymbolAddress((void**)&msgh2, g_msg_h2);
    cudaGetSymbolAddress((void**)&wfc1,  g_wfc1_h2);
    cudaGetSymbolAddress((void**)&wih,   g_wih_h2);
    cudaGetSymbolAddress((void**)&whh,   g_whh_h2);
    cudaGetSymbolAddress((void**)&wq2,   g_wq_h2);
    cudaGetSymbolAddress((void**)&wp1,   g_wp1_h2);

    static bool attr_done = false;
    if (!attr_done) {
        cudaFuncSetAttribute(tgemm_h2, cudaFuncAttributeMaxDynamicSharedMemorySize, TG_SMEM);
        attr_done = true;
    }

    const int MYT = MT_;   // 512

    // weight packs/splits (tiny)
    pack_qkvg<<<(QKVG_N * HID + 255) / 256, 256>>>(q_w, q_b, k_w, k_b, v_w, v_b, g_w, g_b);
    {
        int t1 = 2 * 16 * 512;
        int t2 = 6 * 16 * 512;
        int t3 = 2 * 20 * 512;
        split_w<<<(t1 + 255) / 256, 256>>>(fc1_w, wfc1, HID, IN_DIM, t1);
        split_w<<<(t2 + 255) / 256, 256>>>(w_ih, wih, 3 * HID, HID, t2);
        split_w<<<(t2 + 255) / 256, 256>>>(w_hh, whh, 3 * HID, HID, t2);
        split_w<<<(t1 + 255) / 256, 256>>>(wq, wq2, QKVG_N, HID, t1);
        split_w<<<(t3 + 255) / 256, 256>>>(p1_w, wp1, HID, HID + NH * CV, t3);
    }
    // input splits (256 threads per AF block)
    {
        int ta = MT_ * 16 * 256;
        split_a<<<(ta + 255) / 256, 256>>>(inputs, inh2, IN_DIM, ta);
        split_a<<<(ta + 255) / 256, 256>>>(hidden, hidh2, HID, ta);
    }

    // x = relu(fc1) -> x_h2 (AF, KT=16)
    tgemm_h2<<<dim3(2, MYT), 256, TG_SMEM>>>(
        inh2, inh2, 16, 0, wfc1, fc1_b, nullptr, xh2, 16, 0, HID, M_RELU_AF);
    // gi / gh (fp32)
    tgemm_h2<<<dim3(6, MYT), 256, TG_SMEM>>>(
        xh2, xh2, 16, 0, wih, b_ih, gi, nullptr, 0, 3 * HID, 3 * HID, M_NONE);
    tgemm_h2<<<dim3(6, MYT), 256, TG_SMEM>>>(
        hidh2, hidh2, 16, 0, whh, b_hh, gh, nullptr, 0, 3 * HID, 3 * HID, M_NONE);
    // h (fp32 out + coalesced AF)
    gru_gates<<<(ROWS * (HID / 8) + 255) / 256, 256>>>(gi, gh, hidden, hout, hh2);
    // qkvg (fp32, sigmoid on gate cols)
    tgemm_h2<<<dim3(2, MYT), 256, TG_SMEM>>>(
        hh2, hh2, 16, 0, wq2, bq, qkvg, nullptr, 0, QKVG_N, QKVG_N, M_QKVG);
    // attention -> msg_h2 (AF, KT=4)
    attention_kernel<<<BS_, 128>>>(qkvg, msgh2);
    // p1 = relu([h | msg] @ p1_w^T + b)  (split-A: 16 + 4 chunks)
    tgemm_h2<<<dim3(2, MYT), 256, TG_SMEM>>>(
        hh2, msgh2, 16, 4, wp1, p1_b, p1, nullptr, 0, HID, HID, M_RELU);
    // logits (SIMT fp32)
    gemm8x8<64><<<dim3(1, ROWS / BM), 256>>>(p1, p2_w, p2_b, logits, NACT, NACT, HID, HID);
}